// round 13
// baseline (speedup 1.0000x reference)
#include <cuda_runtime.h>
#include <math.h>
#include <stdint.h>

#define BB 2
#define SS 2048
#define HH 1024
#define FF 2816
#define EE 8
#define KK 2
#define TT (BB*SS)
#define SLOTS (TT*KK)
#define BM 128
#define PADMAX (SLOTS + EE*BM)    // 9216
#define RT_MAX (PADMAX/BM)        // 72
#define KQ_H (HH/4)               // 256 k-quads (gemm1)
#define KQ_F (FF/4)               // 704 k-quads (gemm2)
#define PIT_A 132
#define PIT_B 68

__device__ float g_h1[(size_t)PADMAX * FF];
__device__ float g_y [(size_t)PADMAX * HH];
__device__ uint2 g_qx [(size_t)TT * KQ_H];
__device__ uint2 g_qwgu[(size_t)EE * KQ_H * 2 * FF];
__device__ uint2 g_qwd[(size_t)EE * KQ_F * HH];
__device__ uint2 g_qh1[(size_t)PADMAX * KQ_F];
__device__ float g_sx[TT];
__device__ float g_sgu[(size_t)EE * 2 * FF];
__device__ float g_sd[(size_t)EE * HH];
__device__ float g_sh1[PADMAX];
__device__ int   g_count[EE];
__device__ int   g_fill[EE];
__device__ float g_psum[EE];
__device__ int   g_base[EE+1];
__device__ int   g_sorted_token[PADMAX];
__device__ int   g_slot_row[SLOTS];
__device__ int   g_tok_e[SLOTS];
__device__ float g_tok_w[SLOTS];

// quantize 4 values: q1 = rint(127 x / s), q2 = rint(127*(127x/s - q1))
__device__ __forceinline__ uint2 qpack(float x0, float x1, float x2, float x3, float inv_s) {
    float xs[4] = {x0, x1, x2, x3};
    uint32_t w1 = 0, w2 = 0;
#pragma unroll
    for (int i = 0; i < 4; i++) {
        float t = xs[i] * inv_s;
        float r1 = rintf(t);
        int q1 = (int)r1;
        int q2 = (int)rintf((t - r1) * 127.f);
        w1 |= ((uint32_t)q1 & 0xff) << (8*i);
        w2 |= ((uint32_t)q2 & 0xff) << (8*i);
    }
    return make_uint2(w1, w2);
}
__device__ __forceinline__ void mma_s8(int* d, const uint32_t* a, uint32_t b0, uint32_t b1) {
    asm volatile("mma.sync.aligned.m16n8k32.row.col.s32.s8.s8.s32 "
                 "{%0,%1,%2,%3}, {%4,%5,%6,%7}, {%8,%9}, {%0,%1,%2,%3};"
                 : "+r"(d[0]), "+r"(d[1]), "+r"(d[2]), "+r"(d[3])
                 : "r"(a[0]), "r"(a[1]), "r"(a[2]), "r"(a[3]), "r"(b0), "r"(b1));
}

__global__ void init_kernel() {
    int i = blockIdx.x * blockDim.x + threadIdx.x;
    if (i < PADMAX) g_sorted_token[i] = 0;
    if (i < EE) { g_count[i] = 0; g_fill[i] = 0; g_psum[i] = 0.f; }
}

__global__ void router_kernel(const float* __restrict__ x, const float* __restrict__ rw) {
    int t = blockIdx.x;
    __shared__ float sp[128][EE];
    float acc[EE];
#pragma unroll
    for (int e = 0; e < EE; e++) acc[e] = 0.f;
    const float* xt = x + (size_t)t * HH;
    for (int h = threadIdx.x; h < HH; h += 128) {
        float xv = xt[h];
#pragma unroll
        for (int e = 0; e < EE; e++) acc[e] += xv * rw[e*HH + h];
    }
#pragma unroll
    for (int e = 0; e < EE; e++) sp[threadIdx.x][e] = acc[e];
    __syncthreads();
    for (int s = 64; s > 0; s >>= 1) {
        if (threadIdx.x < s)
#pragma unroll
            for (int e = 0; e < EE; e++) sp[threadIdx.x][e] += sp[threadIdx.x + s][e];
        __syncthreads();
    }
    if (threadIdx.x == 0) {
        float lg[EE];
#pragma unroll
        for (int e = 0; e < EE; e++) lg[e] = sp[0][e];
        int i0 = 0;
#pragma unroll
        for (int e = 1; e < EE; e++) if (lg[e] > lg[i0]) i0 = e;
        int i1 = -1;
#pragma unroll
        for (int e = 0; e < EE; e++) {
            if (e == i0) continue;
            if (i1 < 0 || lg[e] > lg[i1]) i1 = e;
        }
        float ex = expf(lg[i1] - lg[i0]);
        g_tok_e[2*t] = i0;  g_tok_e[2*t+1] = i1;
        g_tok_w[2*t] = 1.f/(1.f+ex);  g_tok_w[2*t+1] = ex/(1.f+ex);
        atomicAdd(&g_count[i0], 1);
        atomicAdd(&g_count[i1], 1);
        float m = lg[0];
#pragma unroll
        for (int e = 1; e < EE; e++) m = fmaxf(m, lg[e]);
        float s = 0.f, pe[EE];
#pragma unroll
        for (int e = 0; e < EE; e++) { pe[e] = expf(lg[e] - m); s += pe[e]; }
        float inv = 1.f / s;
#pragma unroll
        for (int e = 0; e < EE; e++) atomicAdd(&g_psum[e], pe[e] * inv);
    }
}

__global__ void setup_kernel(float* __restrict__ out_aux) {
    if (threadIdx.x == 0) {
        int base = 0;
        for (int e = 0; e < EE; e++) {
            g_base[e] = base;
            base += (g_count[e] + BM - 1) & ~(BM - 1);
        }
        g_base[EE] = base;
        float aux = 0.f;
        for (int e = 0; e < EE; e++)
            aux += ((float)g_count[e] / SLOTS) * (g_psum[e] / TT);
        out_aux[0] = aux * EE;
    }
}

__global__ void scatter_kernel() {
    int s = blockIdx.x * blockDim.x + threadIdx.x;
    if (s >= SLOTS) return;
    int e = g_tok_e[s];
    int row = g_base[e] + atomicAdd(&g_fill[e], 1);
    g_sorted_token[row] = s >> 1;
    g_slot_row[s] = row;
}

// ---- scale + quant pack kernels ----
__global__ void rowmax_x(const float* __restrict__ x) {
    int t = blockIdx.x;
    __shared__ float sm[128];
    float m = 0.f;
    const float* xr = x + (size_t)t * HH;
    for (int i = threadIdx.x; i < HH; i += 128) m = fmaxf(m, fabsf(xr[i]));
    sm[threadIdx.x] = m; __syncthreads();
    for (int s = 64; s > 0; s >>= 1) {
        if (threadIdx.x < s) sm[threadIdx.x] = fmaxf(sm[threadIdx.x], sm[threadIdx.x+s]);
        __syncthreads();
    }
    if (threadIdx.x == 0) g_sx[t] = fmaxf(sm[0], 1e-30f);
}
__global__ void pack_x(const float* __restrict__ x) {
    size_t i = (size_t)blockIdx.x * blockDim.x + threadIdx.x;
    if (i >= (size_t)TT * KQ_H) return;
    int t = (int)(i / KQ_H);
    float4 v = *(const float4*)(x + (size_t)t * HH + (i % KQ_H) * 4);
    g_qx[i] = qpack(v.x, v.y, v.z, v.w, 127.f / g_sx[t]);
}
__global__ void colmax_wgu(const float* __restrict__ wg, const float* __restrict__ wu) {
    int i = blockIdx.x * blockDim.x + threadIdx.x;
    if (i >= EE * FF) return;
    int e = i / FF, f = i % FF;
    const float* pg = wg + (size_t)e * HH * FF + f;
    const float* pu = wu + (size_t)e * HH * FF + f;
    float mg = 0.f, mu = 0.f;
    for (int k = 0; k < HH; k++) {
        mg = fmaxf(mg, fabsf(pg[(size_t)k * FF]));
        mu = fmaxf(mu, fabsf(pu[(size_t)k * FF]));
    }
    g_sgu[(size_t)e * 2 * FF + 2*f]     = fmaxf(mg, 1e-30f);
    g_sgu[(size_t)e * 2 * FF + 2*f + 1] = fmaxf(mu, 1e-30f);
}
__global__ void pack_wgu(const float* __restrict__ wg, const float* __restrict__ wu) {
    size_t i = (size_t)blockIdx.x * blockDim.x + threadIdx.x;
    if (i >= (size_t)EE * KQ_H * FF) return;
    int f = (int)(i % FF);
    size_t ek = i / FF;
    int kq = (int)(ek % KQ_H);
    int e  = (int)(ek / KQ_H);
    size_t src = ((size_t)e * HH + 4*kq) * FF + f;
    float invg = 127.f / g_sgu[(size_t)e * 2 * FF + 2*f];
    float invu = 127.f / g_sgu[(size_t)e * 2 * FF + 2*f + 1];
    uint2 qg = qpack(wg[src], wg[src+FF], wg[src+2*FF], wg[src+3*FF], invg);
    uint2 qu = qpack(wu[src], wu[src+FF], wu[src+2*FF], wu[src+3*FF], invu);
    *(uint4*)&g_qwgu[ek * (2*FF) + 2*f] = make_uint4(qg.x, qg.y, qu.x, qu.y);
}
__global__ void colmax_wd(const float* __restrict__ wd) {
    int i = blockIdx.x * blockDim.x + threadIdx.x;
    if (i >= EE * HH) return;
    int e = i / HH, h = i % HH;
    const float* p = wd + (size_t)e * FF * HH + h;
    float m = 0.f;
    for (int k = 0; k < FF; k++) m = fmaxf(m, fabsf(p[(size_t)k * HH]));
    g_sd[i] = fmaxf(m, 1e-30f);
}
__global__ void pack_wd(const float* __restrict__ wd) {
    size_t i = (size_t)blockIdx.x * blockDim.x + threadIdx.x;
    if (i >= (size_t)EE * KQ_F * HH) return;
    int h = (int)(i % HH);
    size_t ek = i / HH;
    int kq = (int)(ek % KQ_F);
    int e  = (int)(ek / KQ_F);
    size_t src = ((size_t)e * FF + 4*kq) * HH + h;
    float inv = 127.f / g_sd[(size_t)e * HH + h];
    g_qwd[i] = qpack(wd[src], wd[src+HH], wd[src+2*HH], wd[src+3*HH], inv);
}
__global__ void rowmax_h1() {
    int r = blockIdx.x;
    if (r >= g_base[EE]) return;
    __shared__ float sm[128];
    float m = 0.f;
    const float* xr = g_h1 + (size_t)r * FF;
    for (int i = threadIdx.x; i < FF; i += 128) m = fmaxf(m, fabsf(xr[i]));
    sm[threadIdx.x] = m; __syncthreads();
    for (int s = 64; s > 0; s >>= 1) {
        if (threadIdx.x < s) sm[threadIdx.x] = fmaxf(sm[threadIdx.x], sm[threadIdx.x+s]);
        __syncthreads();
    }
    if (threadIdx.x == 0) g_sh1[r] = fmaxf(sm[0], 1e-30f);
}
__global__ void pack_h1() {
    size_t i = (size_t)blockIdx.x * blockDim.x + threadIdx.x;
    if (i >= (size_t)PADMAX * KQ_F) return;
    int r = (int)(i / KQ_F);
    if (r >= g_base[EE]) return;
    float4 v = *(const float4*)(g_h1 + (size_t)r * FF + (i % KQ_F) * 4);
    g_qh1[i] = qpack(v.x, v.y, v.z, v.w, 127.f / g_sh1[r]);
}

#define DQC1 (1.f/16129.f)
#define DQC2 (1.f/2048383.f)

// ==== GEMM1: h1 = silu(x@Wg)*(x@Wu). int8 split, CTA 128M x 32F (64 interleaved cols) ====
__global__ __launch_bounds__(256, 2) void gemm1_kernel() {
    int r0 = blockIdx.x * BM;
    if (r0 >= g_base[EE]) return;
    int n0f = blockIdx.y * 32;
    int e = 0;
    while (g_base[e+1] <= r0) e++;

    __shared__ __align__(16) uint2 As[2][8][PIT_A];
    __shared__ __align__(16) uint2 Bs[2][8][PIT_B];
    __shared__ int s_tok[128];
    __shared__ float s_sa[128], s_sb[64];

    int tid = threadIdx.x, lane = tid & 31, wid = tid >> 5;
    if (tid < 128) {
        int tk = g_sorted_token[r0 + tid];
        s_tok[tid] = tk;
        s_sa[tid] = g_sx[tk];
    }
    if (tid < 64) s_sb[tid] = g_sgu[(size_t)e * 2 * FF + 2*n0f + tid];
    __syncthreads();

    int wm = (wid >> 1) * 32, wn = (wid & 1) * 32;
    int fr = lane >> 2, kq = lane & 3;

    int a_row = tid & 127, a_kh = tid >> 7;
    const uint2* abase = g_qx + (size_t)s_tok[a_row] * KQ_H + a_kh * 4;
    int b_kq = tid >> 5, b_c = (tid & 31) * 2;
    const uint2* bbase = g_qwgu + (size_t)e * KQ_H * (2*FF) + 2*n0f + b_c;

    int dm[2][4][4], dxc[2][4][4];
#pragma unroll
    for (int i = 0; i < 2; i++)
#pragma unroll
        for (int j = 0; j < 4; j++)
#pragma unroll
            for (int k = 0; k < 4; k++) { dm[i][j][k] = 0; dxc[i][j][k] = 0; }

    // chunk 0 direct
    {
        uint4 a0 = *(const uint4*)(abase);
        uint4 a1 = *(const uint4*)(abase + 2);
        As[0][a_kh*4+0][a_row] = make_uint2(a0.x, a0.y);
        As[0][a_kh*4+1][a_row] = make_uint2(a0.z, a0.w);
        As[0][a_kh*4+2][a_row] = make_uint2(a1.x, a1.y);
        As[0][a_kh*4+3][a_row] = make_uint2(a1.z, a1.w);
        uint4 b = *(const uint4*)(bbase + (size_t)b_kq * (2*FF));
        *(uint4*)&Bs[0][b_kq][b_c] = b;
    }
    uint4 pa0 = *(const uint4*)(abase + 8);
    uint4 pa1 = *(const uint4*)(abase + 10);
    uint4 pb  = *(const uint4*)(bbase + (size_t)(8 + b_kq) * (2*FF));
    __syncthreads();

    const int chunks = KQ_H / 8;   // 32
    for (int c = 0; c < chunks; c++) {
        int s = c & 1;
        if (c + 1 < chunks) {
            int s1 = s ^ 1;
            As[s1][a_kh*4+0][a_row] = make_uint2(pa0.x, pa0.y);
            As[s1][a_kh*4+1][a_row] = make_uint2(pa0.z, pa0.w);
            As[s1][a_kh*4+2][a_row] = make_uint2(pa1.x, pa1.y);
            As[s1][a_kh*4+3][a_row] = make_uint2(pa1.z, pa1.w);
            *(uint4*)&Bs[s1][b_kq][b_c] = pb;
        }
        if (c + 2 < chunks) {
            pa0 = *(const uint4*)(abase + (size_t)(c+2)*8);
            pa1 = *(const uint4*)(abase + (size_t)(c+2)*8 + 2);
            pb  = *(const uint4*)(bbase + (size_t)((c+2)*8 + b_kq) * (2*FF));
        }
        uint32_t aq1[2][4], aq2[2][4];
#pragma unroll
        for (int mt = 0; mt < 2; mt++) {
            int mb = wm + mt*16 + fr;
            uint2 q0 = As[s][kq][mb],   q1 = As[s][kq][mb+8];
            uint2 q2 = As[s][kq+4][mb], q3 = As[s][kq+4][mb+8];
            aq1[mt][0]=q0.x; aq1[mt][1]=q1.x; aq1[mt][2]=q2.x; aq1[mt][3]=q3.x;
            aq2[mt][0]=q0.y; aq2[mt][1]=q1.y; aq2[mt][2]=q2.y; aq2[mt][3]=q3.y;
        }
#pragma unroll
        for (int nt = 0; nt < 4; nt++) {
            int nn = wn + nt*8 + fr;
            uint2 b0 = Bs[s][kq][nn], b1 = Bs[s][kq+4][nn];
#pragma unroll
            for (int mt = 0; mt < 2; mt++) {
                mma_s8(dm[mt][nt],  aq1[mt], b0.x, b1.x);
                mma_s8(dxc[mt][nt], aq1[mt], b0.y, b1.y);
                mma_s8(dxc[mt][nt], aq2[mt], b0.x, b1.x);
            }
        }
        __syncthreads();
    }

#pragma unroll
    for (int mt = 0; mt < 2; mt++) {
        int rA = wm + mt*16 + fr;
#pragma unroll
        for (int nt = 0; nt < 4; nt++) {
            int c0 = wn + nt*8 + 2*kq;
            int f = n0f + (c0 >> 1);
            float sg = s_sb[c0], su = s_sb[c0+1];
            float gv = s_sa[rA] * sg * ((float)dm[mt][nt][0]*DQC1 + (float)dxc[mt][nt][0]*DQC2);
            float uv = s_sa[rA] * su * ((float)dm[mt][nt][1]*DQC1 + (float)dxc[mt][nt][1]*DQC2);
            g_h1[(size_t)(r0 + rA) * FF + f] = (gv / (1.f + expf(-gv))) * uv;
            gv = s_sa[rA+8] * sg * ((float)dm[mt][nt][2]*DQC1 + (float)dxc[mt][nt][2]*DQC2);
            uv = s_sa[rA+8] * su * ((float)dm[mt][nt][3]*DQC1 + (float)dxc[mt][nt][3]*DQC2);
            g_h1[(size_t)(r0 + rA + 8) * FF + f] = (gv / (1.f + expf(-gv))) * uv;
        }
    }
}

// ==== GEMM2: y = h1 @ Wd. int8 split, CTA 128M x 64N ====
__global__ __launch_bounds__(256, 2) void gemm2_kernel() {
    int r0 = blockIdx.x * BM;
    if (r0 >= g_base[EE]) return;
    int n0 = blockIdx.y * 64;
    int e = 0;
    while (g_base[e+1] <= r0) e++;

    __shared__ __align__(16) uint2 As[2][8][PIT_A];
    __shared__ __align__(16) uint2 Bs[2][8][PIT_B];
    __shared__ float s_sa[128], s_sb[64];

    int tid = threadIdx.x, lane = tid & 31, wid = tid >> 5;
    if (tid < 128) s_sa[tid] = g_sh1[r0 + tid];
    if (tid < 64) s_sb[tid] = g_sd[(size_t)e * HH + n0 + tid];
    __syncthreads();

    int wm = (wid >> 1) * 32, wn = (wid & 1) * 32;
    int fr = lane >> 2, kq = lane & 3;

    int a_row = tid & 127, a_kh = tid >> 7;
    const uint2* abase = g_qh1 + (size_t)(r0 + a_row) * KQ_F + a_kh * 4;
    int b_kq = tid >> 5, b_c = (tid & 31) * 2;
    const uint2* bbase = g_qwd + (size_t)e * KQ_F * HH + n0 + b_c;

    int dm[2][4][4], dxc[2][4][4];
#pragma unroll
    for (int i = 0; i < 2; i++)
#pragma unroll
        for (int j = 0; j < 4; j++)
#pragma unroll
            for (int k = 0; k < 4; k++) { dm[i][j][k] = 0; dxc[i][j][k] = 0; }

    {
        uint4 a0 = *(const uint4*)(abase);
        uint4 a1 = *(const uint4*)(abase + 2);
        As[0][a_kh*4+0][a_row] = make_uint2(a0.x, a0.y);
        As[0][a_kh*4+1][a_row] = make_uint2(a0.z, a0.w);
        As[0][a_kh*4+2][a_row] = make_uint2(a1.x, a1.y);
        As[0][a_kh*4+3][a_row] = make_uint2(a1.z, a1.w);
        uint4 b = *(const uint4*)(bbase + (size_t)b_kq * HH);
        *(uint4*)&Bs[0][b_kq][b_c] = b;
    }
    uint4 pa0 = *(const uint4*)(abase + 8);
    uint4 pa1 = *(const uint4*)(abase + 10);
    uint4 pb  = *(const uint4*)(bbase + (size_t)(8 + b_kq) * HH);
    __syncthreads();

    const int chunks = KQ_F / 8;   // 88
    for (int c = 0; c < chunks; c++) {
        int s = c & 1;
        if (c + 1 < chunks) {
            int s1 = s ^ 1;
            As[s1][a_kh*4+0][a_row] = make_uint2(pa0.x, pa0.y);
            As[s1][a_kh*4+1][a_row] = make_uint2(pa0.z, pa0.w);
            As[s1][a_kh*4+2][a_row] = make_uint2(pa1.x, pa1.y);
            As[s1][a_kh*4+3][a_row] = make_uint2(pa1.z, pa1.w);
            *(uint4*)&Bs[s1][b_kq][b_c] = pb;
        }
        if (c + 2 < chunks) {
            pa0 = *(const uint4*)(abase + (size_t)(c+2)*8);
            pa1 = *(const uint4*)(abase + (size_t)(c+2)*8 + 2);
            pb  = *(const uint4*)(bbase + (size_t)((c+2)*8 + b_kq) * HH);
        }
        uint32_t aq1[2][4], aq2[2][4];
#pragma unroll
        for (int mt = 0; mt < 2; mt++) {
            int mb = wm + mt*16 + fr;
            uint2 q0 = As[s][kq][mb],   q1 = As[s][kq][mb+8];
            uint2 q2 = As[s][kq+4][mb], q3 = As[s][kq+4][mb+8];
            aq1[mt][0]=q0.x; aq1[mt][1]=q1.x; aq1[mt][2]=q2.x; aq1[mt][3]=q3.x;
            aq2[mt][0]=q0.y; aq2[mt][1]=q1.y; aq2[mt][2]=q2.y; aq2[mt][3]=q3.y;
        }
#pragma unroll
        for (int nt = 0; nt < 4; nt++) {
            int nn = wn + nt*8 + fr;
            uint2 b0 = Bs[s][kq][nn], b1 = Bs[s][kq+4][nn];
#pragma unroll
            for (int mt = 0; mt < 2; mt++) {
                mma_s8(dm[mt][nt],  aq1[mt], b0.x, b1.x);
                mma_s8(dxc[mt][nt], aq1[mt], b0.y, b1.y);
                mma_s8(dxc[mt][nt], aq2[mt], b0.x, b1.x);
            }
        }
        __syncthreads();
    }

#pragma unroll
    for (int mt = 0; mt < 2; mt++) {
        int rA = wm + mt*16 + fr;
#pragma unroll
        for (int nt = 0; nt < 4; nt++) {
            int c0 = wn + nt*8 + 2*kq;
            int col = n0 + c0;
            float s0 = s_sb[c0], s1 = s_sb[c0+1];
            float v0 = s_sa[rA] * s0 * ((float)dm[mt][nt][0]*DQC1 + (float)dxc[mt][nt][0]*DQC2);
            float v1 = s_sa[rA] * s1 * ((float)dm[mt][nt][1]*DQC1 + (float)dxc[mt][nt][1]*DQC2);
            *(float2*)&g_y[(size_t)(r0 + rA) * HH + col] = make_float2(v0, v1);
            v0 = s_sa[rA+8] * s0 * ((float)dm[mt][nt][2]*DQC1 + (float)dxc[mt][nt][2]*DQC2);
            v1 = s_sa[rA+8] * s1 * ((float)dm[mt][nt][3]*DQC1 + (float)dxc[mt][nt][3]*DQC2);
            *(float2*)&g_y[(size_t)(r0 + rA + 8) * HH + col] = make_float2(v0, v1);
        }
    }
}

__global__ void combine_kernel(float* __restrict__ out) {
    int i = blockIdx.x * blockDim.x + threadIdx.x;
    if (i >= TT * (HH/4)) return;
    int t = i / (HH/4);
    int c = (i - t * (HH/4)) * 4;
    int r0 = g_slot_row[2*t], r1 = g_slot_row[2*t+1];
    float w0 = g_tok_w[2*t], w1 = g_tok_w[2*t+1];
    float4 y0 = *(const float4*)(g_y + (size_t)r0 * HH + c);
    float4 y1 = *(const float4*)(g_y + (size_t)r1 * HH + c);
    float4 o;
    o.x = w0*y0.x + w1*y1.x;  o.y = w0*y0.y + w1*y1.y;
    o.z = w0*y0.z + w1*y1.z;  o.w = w0*y0.w + w1*y1.w;
    *(float4*)(out + (size_t)t * HH + c) = o;
}

extern "C" void kernel_launch(void* const* d_in, const int* in_sizes, int n_in,
                              void* d_out, int out_size) {
    const float* x  = (const float*)d_in[0];
    const float* rw = (const float*)d_in[1];
    const float* wg = (const float*)d_in[2];
    const float* wu = (const float*)d_in[3];
    const float* wd = (const float*)d_in[4];
    float* out = (float*)d_out;

    init_kernel<<<(PADMAX + 255) / 256, 256>>>();
    router_kernel<<<TT, 128>>>(x, rw);
    setup_kernel<<<1, 32>>>(out + (size_t)TT * HH);
    scatter_kernel<<<(SLOTS + 255) / 256, 256>>>();
    rowmax_x<<<TT, 128>>>(x);
    pack_x<<<(int)(((size_t)TT*KQ_H + 255) / 256), 256>>>(x);
    colmax_wgu<<<(EE*FF + 255) / 256, 256>>>(wg, wu);
    pack_wgu<<<(int)(((size_t)EE*KQ_H*FF + 255) / 256), 256>>>(wg, wu);
    colmax_wd<<<(EE*HH + 255) / 256, 256>>>(wd);
    pack_wd<<<(int)(((size_t)EE*KQ_F*HH + 255) / 256), 256>>>(wd);
    gemm1_kernel<<<dim3(RT_MAX, FF/32), 256>>>();
    rowmax_h1<<<PADMAX, 128>>>();
    pack_h1<<<(int)(((size_t)PADMAX*KQ_F + 255) / 256), 256>>>();
    gemm2_kernel<<<dim3(RT_MAX, HH/64), 256>>>();
    combine_kernel<<<(TT * (HH/4) + 255) / 256, 256>>>(out);
}

// round 14
// speedup vs baseline: 1.7348x; 1.7348x over previous
#include <cuda_runtime.h>
#include <cuda_bf16.h>
#include <math.h>
#include <stdint.h>

#define BB 2
#define SS 2048
#define HH 1024
#define FF 2816
#define EE 8
#define KK 2
#define TT (BB*SS)
#define SLOTS (TT*KK)
#define BM 128
#define PADMAX (SLOTS + EE*BM)    // 9216
#define RT_MAX (PADMAX/BM)        // 72
#define PIT 132                   // uint2 pitch; 2*PIT mod 32 == 8 -> conflict-free fragment LDS

__device__ float g_h1[(size_t)PADMAX * FF];
__device__ float g_y [(size_t)PADMAX * HH];
__device__ int   g_count[EE];
__device__ int   g_fill[EE];
__device__ float g_psum[EE];
__device__ int   g_base[EE+1];
__device__ int   g_sorted_token[PADMAX];
__device__ int   g_slot_row[SLOTS];
__device__ int   g_tok_e[SLOTS];
__device__ float g_tok_w[SLOTS];

// pack two floats (k-even, k-odd) into (hi-pair, lo-pair) bf16x2 words
__device__ __forceinline__ uint2 spb(float x, float y) {
    __nv_bfloat16 hx = __float2bfloat16(x);
    __nv_bfloat16 hy = __float2bfloat16(y);
    __nv_bfloat16 lx = __float2bfloat16(x - __bfloat162float(hx));
    __nv_bfloat16 ly = __float2bfloat16(y - __bfloat162float(hy));
    uint2 r;
    r.x = (uint32_t)__bfloat16_as_ushort(hx) | ((uint32_t)__bfloat16_as_ushort(hy) << 16);
    r.y = (uint32_t)__bfloat16_as_ushort(lx) | ((uint32_t)__bfloat16_as_ushort(ly) << 16);
    return r;
}
__device__ __forceinline__ void mma_bf16(float* d, const uint32_t* a, uint32_t b0, uint32_t b1) {
    asm volatile("mma.sync.aligned.m16n8k16.row.col.f32.bf16.bf16.f32 "
                 "{%0,%1,%2,%3}, {%4,%5,%6,%7}, {%8,%9}, {%0,%1,%2,%3};"
                 : "+f"(d[0]), "+f"(d[1]), "+f"(d[2]), "+f"(d[3])
                 : "r"(a[0]), "r"(a[1]), "r"(a[2]), "r"(a[3]), "r"(b0), "r"(b1));
}

__global__ void init_kernel() {
    int i = blockIdx.x * blockDim.x + threadIdx.x;
    if (i < PADMAX) g_sorted_token[i] = 0;
    if (i < EE) { g_count[i] = 0; g_fill[i] = 0; g_psum[i] = 0.f; }
}

__global__ void router_kernel(const float* __restrict__ x, const float* __restrict__ rw) {
    int t = blockIdx.x;
    __shared__ float sp[128][EE];
    float acc[EE];
#pragma unroll
    for (int e = 0; e < EE; e++) acc[e] = 0.f;
    const float* xt = x + (size_t)t * HH;
    for (int h = threadIdx.x; h < HH; h += 128) {
        float xv = xt[h];
#pragma unroll
        for (int e = 0; e < EE; e++) acc[e] += xv * rw[e*HH + h];
    }
#pragma unroll
    for (int e = 0; e < EE; e++) sp[threadIdx.x][e] = acc[e];
    __syncthreads();
    for (int s = 64; s > 0; s >>= 1) {
        if (threadIdx.x < s)
#pragma unroll
            for (int e = 0; e < EE; e++) sp[threadIdx.x][e] += sp[threadIdx.x + s][e];
        __syncthreads();
    }
    if (threadIdx.x == 0) {
        float lg[EE];
#pragma unroll
        for (int e = 0; e < EE; e++) lg[e] = sp[0][e];
        int i0 = 0;
#pragma unroll
        for (int e = 1; e < EE; e++) if (lg[e] > lg[i0]) i0 = e;
        int i1 = -1;
#pragma unroll
        for (int e = 0; e < EE; e++) {
            if (e == i0) continue;
            if (i1 < 0 || lg[e] > lg[i1]) i1 = e;
        }
        float ex = expf(lg[i1] - lg[i0]);
        g_tok_e[2*t] = i0;  g_tok_e[2*t+1] = i1;
        g_tok_w[2*t] = 1.f/(1.f+ex);  g_tok_w[2*t+1] = ex/(1.f+ex);
        atomicAdd(&g_count[i0], 1);
        atomicAdd(&g_count[i1], 1);
        float m = lg[0];
#pragma unroll
        for (int e = 1; e < EE; e++) m = fmaxf(m, lg[e]);
        float s = 0.f, pe[EE];
#pragma unroll
        for (int e = 0; e < EE; e++) { pe[e] = expf(lg[e] - m); s += pe[e]; }
        float inv = 1.f / s;
#pragma unroll
        for (int e = 0; e < EE; e++) atomicAdd(&g_psum[e], pe[e] * inv);
    }
}

__global__ void setup_kernel(float* __restrict__ out_aux) {
    if (threadIdx.x == 0) {
        int base = 0;
        for (int e = 0; e < EE; e++) {
            g_base[e] = base;
            base += (g_count[e] + BM - 1) & ~(BM - 1);
        }
        g_base[EE] = base;
        float aux = 0.f;
        for (int e = 0; e < EE; e++)
            aux += ((float)g_count[e] / SLOTS) * (g_psum[e] / TT);
        out_aux[0] = aux * EE;
    }
}

__global__ void scatter_kernel() {
    int s = blockIdx.x * blockDim.x + threadIdx.x;
    if (s >= SLOTS) return;
    int e = g_tok_e[s];
    int row = g_base[e] + atomicAdd(&g_fill[e], 1);
    g_sorted_token[row] = s >> 1;
    g_slot_row[s] = row;
}

// ==== GEMM1: h1 = silu(x@Wg)*(x@Wu). 256 thr, CTA 128M x 64F (gate/up interleaved) ====
__global__ __launch_bounds__(256, 2) void gemm1_kernel(
    const float* __restrict__ x, const float* __restrict__ wg, const float* __restrict__ wu)
{
    int r0 = blockIdx.x * BM;
    if (r0 >= g_base[EE]) return;
    int n0f = blockIdx.y * 64;
    int e = 0;
    while (g_base[e+1] <= r0) e++;

    __shared__ __align__(16) uint2 As[2][8][PIT];
    __shared__ __align__(16) uint2 Bs[2][8][PIT];
    __shared__ int s_tok[128];

    int tid = threadIdx.x, lane = tid & 31, wid = tid >> 5;
    if (tid < 128) s_tok[tid] = g_sorted_token[r0 + tid];
    __syncthreads();

    int wm = (wid >> 1) * 32, wn = (wid & 1) * 64;
    int fr = lane >> 2, kq = lane & 3;

    int a_row = tid & 127, a_kh = tid >> 7;
    const float* arow = x + (size_t)s_tok[a_row] * HH + a_kh * 8;
    int b_kp = tid >> 5, b_f = (tid & 31) * 2;
    const float* grow = wg + (size_t)e * HH * FF + n0f + b_f;
    const float* urow = wu + (size_t)e * HH * FF + n0f + b_f;

    float d[2][8][4];
#pragma unroll
    for (int i = 0; i < 2; i++)
#pragma unroll
        for (int j = 0; j < 8; j++)
#pragma unroll
            for (int k = 0; k < 4; k++) d[i][j][k] = 0.f;

#define G1_STS(st, A0, A1, G0, G1v, U0, U1v) do {                               \
    float af_[8] = {(A0).x,(A0).y,(A0).z,(A0).w,(A1).x,(A1).y,(A1).z,(A1).w};   \
    _Pragma("unroll")                                                           \
    for (int j_ = 0; j_ < 4; j_++)                                              \
        As[st][a_kh*4 + j_][a_row] = spb(af_[2*j_], af_[2*j_+1]);               \
    uint2 c0_ = spb((G0).x, (G1v).x);                                           \
    uint2 c1_ = spb((U0).x, (U1v).x);                                           \
    uint2 c2_ = spb((G0).y, (G1v).y);                                           \
    uint2 c3_ = spb((U0).y, (U1v).y);                                           \
    *(uint4*)&Bs[st][b_kp][2*b_f]     = make_uint4(c0_.x, c0_.y, c1_.x, c1_.y); \
    *(uint4*)&Bs[st][b_kp][2*b_f + 2] = make_uint4(c2_.x, c2_.y, c3_.x, c3_.y); \
} while (0)

    {
        float4 a0 = *(const float4*)(arow), a1 = *(const float4*)(arow + 4);
        size_t k0 = (size_t)(2*b_kp) * FF;
        float2 g0 = *(const float2*)(grow + k0),      g1 = *(const float2*)(grow + k0 + FF);
        float2 u0 = *(const float2*)(urow + k0),      u1 = *(const float2*)(urow + k0 + FF);
        G1_STS(0, a0, a1, g0, g1, u0, u1);
    }
    float4 pa0 = *(const float4*)(arow + 16), pa1 = *(const float4*)(arow + 20);
    float2 pg0, pg1, pu0, pu1;
    {
        size_t k0 = (size_t)(16 + 2*b_kp) * FF;
        pg0 = *(const float2*)(grow + k0);  pg1 = *(const float2*)(grow + k0 + FF);
        pu0 = *(const float2*)(urow + k0);  pu1 = *(const float2*)(urow + k0 + FF);
    }
    __syncthreads();

    const int chunks = HH / 16;   // 64
    for (int c = 0; c < chunks; c++) {
        int s = c & 1;
        if (c + 1 < chunks) {
            int s1 = s ^ 1;
            G1_STS(s1, pa0, pa1, pg0, pg1, pu0, pu1);
        }
        if (c + 2 < chunks) {
            pa0 = *(const float4*)(arow + (c+2)*16);
            pa1 = *(const float4*)(arow + (c+2)*16 + 4);
            size_t k0 = (size_t)((c+2)*16 + 2*b_kp) * FF;
            pg0 = *(const float2*)(grow + k0);  pg1 = *(const float2*)(grow + k0 + FF);
            pu0 = *(const float2*)(urow + k0);  pu1 = *(const float2*)(urow + k0 + FF);
        }
        uint32_t ahi[2][4], alo[2][4];
#pragma unroll
        for (int mt = 0; mt < 2; mt++) {
            int mb = wm + mt*16 + fr;
            uint2 q0 = As[s][kq][mb],   q1 = As[s][kq][mb+8];
            uint2 q2 = As[s][kq+4][mb], q3 = As[s][kq+4][mb+8];
            ahi[mt][0]=q0.x; ahi[mt][1]=q1.x; ahi[mt][2]=q2.x; ahi[mt][3]=q3.x;
            alo[mt][0]=q0.y; alo[mt][1]=q1.y; alo[mt][2]=q2.y; alo[mt][3]=q3.y;
        }
#pragma unroll
        for (int nt = 0; nt < 8; nt++) {
            int nn = wn + nt*8 + fr;
            uint2 b0 = Bs[s][kq][nn], b1 = Bs[s][kq+4][nn];
#pragma unroll
            for (int mt = 0; mt < 2; mt++) {
                mma_bf16(d[mt][nt], ahi[mt], b0.x, b1.x);
                mma_bf16(d[mt][nt], ahi[mt], b0.y, b1.y);
                mma_bf16(d[mt][nt], alo[mt], b0.x, b1.x);
            }
        }
        __syncthreads();
    }
#undef G1_STS

#pragma unroll
    for (int mt = 0; mt < 2; mt++) {
        int row = r0 + wm + mt*16 + fr;
#pragma unroll
        for (int nt = 0; nt < 8; nt++) {
            int f = n0f + (wn >> 1) + nt*4 + kq;
            float gv = d[mt][nt][0], uv = d[mt][nt][1];
            g_h1[(size_t)row * FF + f] = (gv / (1.f + expf(-gv))) * uv;
            gv = d[mt][nt][2]; uv = d[mt][nt][3];
            g_h1[(size_t)(row + 8) * FF + f] = (gv / (1.f + expf(-gv))) * uv;
        }
    }
}

// ==== GEMM2: y = h1 @ Wd. 256 thr, CTA 128M x 128N ====
__global__ __launch_bounds__(256, 2) void gemm2_kernel(const float* __restrict__ wd)
{
    int r0 = blockIdx.x * BM;
    if (r0 >= g_base[EE]) return;
    int n0 = blockIdx.y * 128;
    int e = 0;
    while (g_base[e+1] <= r0) e++;

    __shared__ __align__(16) uint2 As[2][8][PIT];
    __shared__ __align__(16) uint2 Bs[2][8][PIT];

    int tid = threadIdx.x, lane = tid & 31, wid = tid >> 5;
    int wm = (wid >> 1) * 32, wn = (wid & 1) * 64;
    int fr = lane >> 2, kq = lane & 3;

    int a_row = tid & 127, a_kh = tid >> 7;
    const float* arow = g_h1 + (size_t)(r0 + a_row) * FF + a_kh * 8;
    int b_kp = tid >> 5, b_n = (tid & 31) * 4;
    const float* brow = wd + (size_t)e * FF * HH + n0 + b_n;

    float d[2][8][4];
#pragma unroll
    for (int i = 0; i < 2; i++)
#pragma unroll
        for (int j = 0; j < 8; j++)
#pragma unroll
            for (int k = 0; k < 4; k++) d[i][j][k] = 0.f;

#define G2_STS(st, A0, A1, B0, B1v) do {                                        \
    float af_[8] = {(A0).x,(A0).y,(A0).z,(A0).w,(A1).x,(A1).y,(A1).z,(A1).w};   \
    _Pragma("unroll")                                                           \
    for (int j_ = 0; j_ < 4; j_++)                                              \
        As[st][a_kh*4 + j_][a_row] = spb(af_[2*j_], af_[2*j_+1]);               \
    uint2 c0_ = spb((B0).x, (B1v).x);                                           \
    uint2 c1_ = spb((B0).y, (B1v).y);                                           \
    uint2 c2_ = spb((B0).z, (B1v).z);                                           \
    uint2 c3_ = spb((B0).w, (B1v).w);                                           \
    *(uint4*)&Bs[st][b_kp][b_n]     = make_uint4(c0_.x, c0_.y, c1_.x, c1_.y);   \
    *(uint4*)&Bs[st][b_kp][b_n + 2] = make_uint4(c2_.x, c2_.y, c3_.x, c3_.y);   \
} while (0)

    {
        float4 a0 = *(const float4*)(arow), a1 = *(const float4*)(arow + 4);
        size_t k0 = (size_t)(2*b_kp) * HH;
        float4 b0 = *(const float4*)(brow + k0), b1 = *(const float4*)(brow + k0 + HH);
        G2_STS(0, a0, a1, b0, b1);
    }
    float4 pa0 = *(const float4*)(arow + 16), pa1 = *(const float4*)(arow + 20);
    float4 pb0, pb1;
    {
        size_t k0 = (size_t)(16 + 2*b_kp) * HH;
        pb0 = *(const float4*)(brow + k0);  pb1 = *(const float4*)(brow + k0 + HH);
    }
    __syncthreads();

    const int chunks = FF / 16;   // 176
    for (int c = 0; c < chunks; c++) {
        int s = c & 1;
        if (c + 1 < chunks) {
            int s1 = s ^ 1;
            G2_STS(s1, pa0, pa1, pb0, pb1);
        }
        if (c + 2 < chunks) {
            pa0 = *(const float4*)(arow + (c+2)*16);
            pa1 = *(const float4*)(arow + (c+2)*16 + 4);
            size_t k0 = (size_t)((c+2)*16 + 2*b_kp) * HH;
            pb0 = *(const float4*)(brow + k0);
            pb1 = *(const float4*)(brow + k0 + HH);
        }
        uint32_t ahi[2][4], alo[2][4];
#pragma unroll
        for (int mt = 0; mt < 2; mt++) {
            int mb = wm + mt*16 + fr;
            uint2 q0 = As[s][kq][mb],   q1 = As[s][kq][mb+8];
            uint2 q2 = As[s][kq+4][mb], q3 = As[s][kq+4][mb+8];
            ahi[mt][0]=q0.x; ahi[mt][1]=q1.x; ahi[mt][2]=q2.x; ahi[mt][3]=q3.x;
            alo[mt][0]=q0.y; alo[mt][1]=q1.y; alo[mt][2]=q2.y; alo[mt][3]=q3.y;
        }
#pragma unroll
        for (int nt = 0; nt < 8; nt++) {
            int nn = wn + nt*8 + fr;
            uint2 b0 = Bs[s][kq][nn], b1 = Bs[s][kq+4][nn];
#pragma unroll
            for (int mt = 0; mt < 2; mt++) {
                mma_bf16(d[mt][nt], ahi[mt], b0.x, b1.x);
                mma_bf16(d[mt][nt], ahi[mt], b0.y, b1.y);
                mma_bf16(d[mt][nt], alo[mt], b0.x, b1.x);
            }
        }
        __syncthreads();
    }
#undef G2_STS

#pragma unroll
    for (int mt = 0; mt < 2; mt++) {
        int row = r0 + wm + mt*16 + fr;
#pragma unroll
        for (int nt = 0; nt < 8; nt++) {
            int col = n0 + wn + nt*8 + 2*kq;
            *(float2*)&g_y[(size_t)row * HH + col]       = make_float2(d[mt][nt][0], d[mt][nt][1]);
            *(float2*)&g_y[(size_t)(row + 8) * HH + col] = make_float2(d[mt][nt][2], d[mt][nt][3]);
        }
    }
}

__global__ void combine_kernel(float* __restrict__ out) {
    int i = blockIdx.x * blockDim.x + threadIdx.x;
    if (i >= TT * (HH/4)) return;
    int t = i / (HH/4);
    int c = (i - t * (HH/4)) * 4;
    int r0 = g_slot_row[2*t], r1 = g_slot_row[2*t+1];
    float w0 = g_tok_w[2*t], w1 = g_tok_w[2*t+1];
    float4 y0 = *(const float4*)(g_y + (size_t)r0 * HH + c);
    float4 y1 = *(const float4*)(g_y + (size_t)r1 * HH + c);
    float4 o;
    o.x = w0*y0.x + w1*y1.x;  o.y = w0*y0.y + w1*y1.y;
    o.z = w0*y0.z + w1*y1.z;  o.w = w0*y0.w + w1*y1.w;
    *(float4*)(out + (size_t)t * HH + c) = o;
}

extern "C" void kernel_launch(void* const* d_in, const int* in_sizes, int n_in,
                              void* d_out, int out_size) {
    const float* x  = (const float*)d_in[0];
    const float* rw = (const float*)d_in[1];
    const float* wg = (const float*)d_in[2];
    const float* wu = (const float*)d_in[3];
    const float* wd = (const float*)d_in[4];
    float* out = (float*)d_out;

    init_kernel<<<(PADMAX + 255) / 256, 256>>>();
    router_kernel<<<TT, 128>>>(x, rw);
    setup_kernel<<<1, 32>>>(out + (size_t)TT * HH);
    scatter_kernel<<<(SLOTS + 255) / 256, 256>>>();
    gemm1_kernel<<<dim3(RT_MAX, FF/64), 256>>>(x, wg, wu);
    gemm2_kernel<<<dim3(RT_MAX, HH/128), 256>>>(wd);
    combine_kernel<<<(TT * (HH/4) + 255) / 256, 256>>>(out);
}